// round 7
// baseline (speedup 1.0000x reference)
#include <cuda_runtime.h>
#include <cuda_fp16.h>
#include <cuda_bf16.h>
#include <cstdint>

// Problem constants
#define T_DIM 4096
#define K_DIM 4096
#define N_DIM 11008
#define KPACK (K_DIM / 2)   // packed int4 bytes per row

constexpr int BM = 128;
constexpr int BN = 128;
constexpr int BK = 64;          // unpacked K elements per tile
constexpr int THREADS = 256;
constexpr int SSTRIDE = 36;     // uint32 words per smem row (32 data = 64 bf16, + 4 pad)

// Static scratch: packed-int4 byte streams rebuilt from the harness's int32 arrays
// (harness type system is {float32, int32, bfloat16}; jnp.int8 arrives as int32,
// one packed byte per element). __device__ globals are the allowed scratch path.
__device__ int8_t g_pqx[(size_t)T_DIM * KPACK];   // 8.4 MB
__device__ int8_t g_wq [(size_t)N_DIM * KPACK];   // 22.5 MB

// Repack: 4 int32 (one byte of payload each) -> 4 packed bytes (one uint32 store).
__global__ void repack_kernel(const int* __restrict__ src, int8_t* __restrict__ dst,
                              int n4) {
    int idx = blockIdx.x * blockDim.x + threadIdx.x;
    if (idx >= n4) return;
    uint4 w = reinterpret_cast<const uint4*>(src)[idx];
    unsigned t01 = __byte_perm(w.x, w.y, 0x0040);  // b0=w.x.b0, b1=w.y.b0
    unsigned t23 = __byte_perm(w.z, w.w, 0x4000);  // b2=w.z.b0, b3=w.w.b0
    reinterpret_cast<unsigned*>(dst)[idx] = __byte_perm(t01, t23, 0x7610);
}

// Unpack 16 packed int4 bytes (uint4) -> 32 bf16 values (16 uint32 words), k-ordered
// (low nibble = even k first). Trick: m = nibble ^ 8 in [0,15]; bf16 (0x4300|m) = 128+m
// exactly; subtract 136 -> signed value m-8 = v. Exact for all 16 codes.
__device__ __forceinline__ void unpack16_bf16_store(unsigned* dst, uint4 v) {
    const unsigned MG = 0x43004300u;
    const __nv_bfloat162 bias = __float2bfloat162_rn(136.0f);
    unsigned w[4] = {v.x ^ 0x88888888u, v.y ^ 0x88888888u,
                     v.z ^ 0x88888888u, v.w ^ 0x88888888u};
#pragma unroll
    for (int i = 0; i < 4; i++) {
        unsigned x = w[i];
        unsigned u0 = ( x        & 0xFu) | ((x << 12) & 0x000F0000u) | MG;
        unsigned u1 = ((x >>  8) & 0xFu) | ((x <<  4) & 0x000F0000u) | MG;
        unsigned u2 = ((x >> 16) & 0xFu) | ((x >>  4) & 0x000F0000u) | MG;
        unsigned u3 = ((x >> 24) & 0xFu) | ((x >> 12) & 0x000F0000u) | MG;
        __nv_bfloat162 r0 = __hsub2(*reinterpret_cast<__nv_bfloat162*>(&u0), bias);
        __nv_bfloat162 r1 = __hsub2(*reinterpret_cast<__nv_bfloat162*>(&u1), bias);
        __nv_bfloat162 r2 = __hsub2(*reinterpret_cast<__nv_bfloat162*>(&u2), bias);
        __nv_bfloat162 r3 = __hsub2(*reinterpret_cast<__nv_bfloat162*>(&u3), bias);
        uint4 o;
        o.x = *reinterpret_cast<unsigned*>(&r0);
        o.y = *reinterpret_cast<unsigned*>(&r1);
        o.z = *reinterpret_cast<unsigned*>(&r2);
        o.w = *reinterpret_cast<unsigned*>(&r3);
        reinterpret_cast<uint4*>(dst + i * 4)[0] = o;
    }
}

// Round through fp16 (matching reference's astype(float16)) then widen to fp32.
__device__ __forceinline__ float h16(float v) {
    return __half2float(__float2half_rn(v));
}

__global__ void __launch_bounds__(THREADS)
linear4bit_kernel(const int8_t* __restrict__ pqx,
                  const float*  __restrict__ sx,
                  const int8_t* __restrict__ wq,
                  const float*  __restrict__ ws,
                  float*        __restrict__ out) {
    __shared__ unsigned As[BM * SSTRIDE];
    __shared__ unsigned Bs[BN * SSTRIDE];

    const int tid  = threadIdx.x;
    const int lane = tid & 31;
    const int warp = tid >> 5;
    const int tig  = lane & 3;          // thread-in-group
    const int grp  = lane >> 2;         // groupID
    const int warpRow = (warp >> 2) * 64;  // 2 warp-rows of 64
    const int warpCol = (warp & 3) * 32;   // 4 warp-cols of 32
    const int bm = blockIdx.y * BM;
    const int bn = blockIdx.x * BN;

    // fp32 accumulators: 4x4 tiles of m16n8, 4 regs each (exact integer sums)
    float acc[4][4][4];
#pragma unroll
    for (int i = 0; i < 4; i++)
#pragma unroll
        for (int j = 0; j < 4; j++)
#pragma unroll
            for (int r = 0; r < 4; r++) acc[i][j][r] = 0.0f;

    // Loader mapping: 256 threads, each loads 16 packed bytes (= 32 k-values)
    const int lrow = tid >> 1;       // 0..127
    const int lseg = tid & 1;        // which 16-byte half of the 32 packed bytes/row

    const size_t a_base = (size_t)(bm + lrow) * KPACK + (size_t)lseg * 16;
    const size_t b_base = (size_t)(bn + lrow) * KPACK + (size_t)lseg * 16;

    for (int kb = 0; kb < K_DIM / BK; kb++) {
        uint4 va = *reinterpret_cast<const uint4*>(pqx + a_base + kb * (BK / 2));
        uint4 vb = *reinterpret_cast<const uint4*>(wq  + b_base + kb * (BK / 2));

        __syncthreads();  // previous iteration's MMAs done before overwrite
        unpack16_bf16_store(As + lrow * SSTRIDE + lseg * 16, va);
        unpack16_bf16_store(Bs + lrow * SSTRIDE + lseg * 16, vb);
        __syncthreads();

#pragma unroll
        for (int ks = 0; ks < 4; ks++) {  // four k16 steps per BK=64
            unsigned a[4][4];
            unsigned b[4][2];
#pragma unroll
            for (int mi = 0; mi < 4; mi++) {
                const int r0 = warpRow + mi * 16 + grp;
                const unsigned* p = As + r0 * SSTRIDE + ks * 8 + tig;
                a[mi][0] = p[0];
                a[mi][1] = p[8 * SSTRIDE];
                a[mi][2] = p[4];
                a[mi][3] = p[8 * SSTRIDE + 4];
            }
#pragma unroll
            for (int ni = 0; ni < 4; ni++) {
                const int c0 = warpCol + ni * 8 + grp;
                const unsigned* p = Bs + c0 * SSTRIDE + ks * 8 + tig;
                b[ni][0] = p[0];
                b[ni][1] = p[4];
            }
#pragma unroll
            for (int mi = 0; mi < 4; mi++) {
#pragma unroll
                for (int ni = 0; ni < 4; ni++) {
                    asm volatile(
                        "mma.sync.aligned.m16n8k16.row.col.f32.bf16.bf16.f32 "
                        "{%0,%1,%2,%3}, {%4,%5,%6,%7}, {%8,%9}, {%0,%1,%2,%3};\n"
                        : "+f"(acc[mi][ni][0]), "+f"(acc[mi][ni][1]),
                          "+f"(acc[mi][ni][2]), "+f"(acc[mi][ni][3])
                        : "r"(a[mi][0]), "r"(a[mi][1]), "r"(a[mi][2]), "r"(a[mi][3]),
                          "r"(b[ni][0]), "r"(b[ni][1]));
                }
            }
        }
    }

    // Epilogue: fused dequant, fp16-round, store as float32 (harness __output__ dtype).
#pragma unroll
    for (int mi = 0; mi < 4; mi++) {
        const int r0 = bm + warpRow + mi * 16 + grp;
        const float s0 = sx[r0];
        const float s1 = sx[r0 + 8];
#pragma unroll
        for (int ni = 0; ni < 4; ni++) {
            const int c = bn + warpCol + ni * 8 + (tig << 1);
            const float w0 = ws[c];
            const float w1 = ws[c + 1];
            float2 v0 = make_float2(h16(acc[mi][ni][0] * s0 * w0),
                                    h16(acc[mi][ni][1] * s0 * w1));
            float2 v1 = make_float2(h16(acc[mi][ni][2] * s1 * w0),
                                    h16(acc[mi][ni][3] * s1 * w1));
            *reinterpret_cast<float2*>(out + (size_t)r0 * N_DIM + c)       = v0;
            *reinterpret_cast<float2*>(out + (size_t)(r0 + 8) * N_DIM + c) = v1;
        }
    }
}

extern "C" void kernel_launch(void* const* d_in, const int* in_sizes, int n_in,
                              void* d_out, int out_size) {
    // Resolve inputs BY ELEMENT COUNT (pairwise distinct):
    //   pq_x          : T*K/2 = 8,388,608  (int32 in harness, 1 packed byte/elem)
    //   weight        : N*K/2 = 22,544,384 (int32 in harness, 1 packed byte/elem)
    //   scales_x      : T     = 4,096      (float32)
    //   weight_scales : N     = 11,008     (float32)
    const int* pqx32 = nullptr;
    const int* wq32  = nullptr;
    const float* sx  = nullptr;
    const float* ws  = nullptr;
    for (int i = 0; i < n_in; i++) {
        long long s = (long long)in_sizes[i];
        if      (s == (long long)T_DIM * KPACK) pqx32 = (const int*)d_in[i];
        else if (s == (long long)N_DIM * KPACK) wq32  = (const int*)d_in[i];
        else if (s == (long long)T_DIM)         sx    = (const float*)d_in[i];
        else if (s == (long long)N_DIM)         ws    = (const float*)d_in[i];
    }
    if (!pqx32 || !wq32 || !sx || !ws) {
        pqx32 = (const int*)d_in[0];
        sx    = (const float*)d_in[1];
        wq32  = (const int*)d_in[2];
        ws    = (const float*)d_in[3];
    }
    float* out = (float*)d_out;  // [1, T, N] float32

    // Prologue: rebuild packed-int4 byte streams from int32 arrays.
    int8_t* pqx_dev = nullptr;
    int8_t* wq_dev  = nullptr;
    cudaGetSymbolAddress((void**)&pqx_dev, g_pqx);
    cudaGetSymbolAddress((void**)&wq_dev,  g_wq);

    const int n4_a = (T_DIM * KPACK) / 4;   // 2,097,152
    const int n4_b = (N_DIM * KPACK) / 4;   // 5,636,096
    repack_kernel<<<(n4_a + 255) / 256, 256>>>(pqx32, pqx_dev, n4_a);
    repack_kernel<<<(n4_b + 255) / 256, 256>>>(wq32,  wq_dev,  n4_b);

    dim3 grid(N_DIM / BN, T_DIM / BM);  // 86 x 32
    linear4bit_kernel<<<grid, THREADS>>>(pqx_dev, sx, wq_dev, ws, out);
}

// round 9
// speedup vs baseline: 1.0323x; 1.0323x over previous
#include <cuda_runtime.h>
#include <cuda_fp16.h>
#include <cuda_bf16.h>
#include <cstdint>

// Problem constants
#define T_DIM 4096
#define K_DIM 4096
#define N_DIM 11008
#define KPACK (K_DIM / 2)

constexpr int BM = 128;
constexpr int BN = 128;
constexpr int BK = 64;              // bf16 K elements per stage
constexpr int THREADS = 256;
constexpr int SSTRIDE = 36;         // words per row: 32 data (64 bf16) + 4 pad
constexpr int STAGE_WORDS = BM * SSTRIDE;      // 4608 words = 18432 B per operand
constexpr int STAGES = 3;
constexpr int B_BASE = STAGES * STAGE_WORDS;   // B region starts after A stages
constexpr int SMEM_WORDS = 2 * STAGES * STAGE_WORDS;   // 27648 words = 110592 B
constexpr int NUM_KB = K_DIM / BK;  // 64

// Static scratch: planar bf16 operands, converted ONCE in a prologue kernel.
__device__ __nv_bfloat16 g_a[(size_t)T_DIM * K_DIM];   // 32 MB
__device__ __nv_bfloat16 g_w[(size_t)N_DIM * K_DIM];   // 88 MB

// ---------------------------------------------------------------------------
// Repack: 4 int32 (one packed int4-pair byte each) -> 8 bf16 (one uint4 store).
// nibble n: m = n^8 in [0,15]; bf16 bits (0x4300|m) == 128+m exactly; -136 -> signed n.
__global__ void repack_bf16_kernel(const int* __restrict__ src,
                                   unsigned* __restrict__ dst, int n4) {
    int idx = blockIdx.x * blockDim.x + threadIdx.x;
    if (idx >= n4) return;
    uint4 w = reinterpret_cast<const uint4*>(src)[idx];
    unsigned t01 = __byte_perm(w.x, w.y, 0x0040);
    unsigned t23 = __byte_perm(w.z, w.w, 0x4000);
    unsigned x   = __byte_perm(t01, t23, 0x7610) ^ 0x88888888u;
    const unsigned MG = 0x43004300u;
    const __nv_bfloat162 bias = __float2bfloat162_rn(136.0f);
    unsigned u0 = ( x        & 0xFu) | ((x << 12) & 0x000F0000u) | MG;
    unsigned u1 = ((x >>  8) & 0xFu) | ((x <<  4) & 0x000F0000u) | MG;
    unsigned u2 = ((x >> 16) & 0xFu) | ((x >>  4) & 0x000F0000u) | MG;
    unsigned u3 = ((x >> 24) & 0xFu) | ((x >> 12) & 0x000F0000u) | MG;
    __nv_bfloat162 r0 = __hsub2(*reinterpret_cast<__nv_bfloat162*>(&u0), bias);
    __nv_bfloat162 r1 = __hsub2(*reinterpret_cast<__nv_bfloat162*>(&u1), bias);
    __nv_bfloat162 r2 = __hsub2(*reinterpret_cast<__nv_bfloat162*>(&u2), bias);
    __nv_bfloat162 r3 = __hsub2(*reinterpret_cast<__nv_bfloat162*>(&u3), bias);
    uint4 o;
    o.x = *reinterpret_cast<unsigned*>(&r0);
    o.y = *reinterpret_cast<unsigned*>(&r1);
    o.z = *reinterpret_cast<unsigned*>(&r2);
    o.w = *reinterpret_cast<unsigned*>(&r3);
    reinterpret_cast<uint4*>(dst)[idx] = o;
}

// ---------------------------------------------------------------------------
__device__ __forceinline__ uint32_t smem_u32(const void* p) {
    uint32_t a;
    asm("{ .reg .u64 t; cvta.to.shared.u64 t, %1; cvt.u32.u64 %0, t; }" : "=r"(a) : "l"(p));
    return a;
}
__device__ __forceinline__ void cp_async16(uint32_t dst, const void* src) {
    asm volatile("cp.async.cg.shared.global [%0], [%1], 16;\n" :: "r"(dst), "l"(src));
}
#define CP_COMMIT() asm volatile("cp.async.commit_group;" ::: "memory")
#define CP_WAIT(n)  asm volatile("cp.async.wait_group %0;" :: "n"(n) : "memory")

__device__ __forceinline__ float h16(float v) {
    return __half2float(__float2half_rn(v));
}

__global__ void __launch_bounds__(THREADS, 2)
gemm_hmma_pipe_kernel(const __nv_bfloat16* __restrict__ A,
                      const float*  __restrict__ sx,
                      const __nv_bfloat16* __restrict__ W,
                      const float*  __restrict__ ws,
                      float*        __restrict__ out) {
    extern __shared__ unsigned smem[];
    const uint32_t sb = smem_u32(smem);

    const int tid  = threadIdx.x;
    const int lane = tid & 31;
    const int warp = tid >> 5;
    const int tig  = lane & 3;
    const int grp  = lane >> 2;
    const int warpRow = (warp >> 2) * 64;
    const int warpCol = (warp & 3) * 32;
    const int bm = blockIdx.y * BM;
    const int bn = blockIdx.x * BN;

    float acc[4][4][4];
#pragma unroll
    for (int i = 0; i < 4; i++)
#pragma unroll
        for (int j = 0; j < 4; j++)
#pragma unroll
            for (int r = 0; r < 4; r++) acc[i][j][r] = 0.0f;

    // cp.async loader mapping: 1024 chunks of 16B per operand per stage; 4/thread.
    // chunk c: row = c>>3 (0..127), seg = c&7 (16B within 128B of K-data).
    const int seg  = tid & 7;
    const int row0 = tid >> 3;       // 0..31; chunks at row0 + 32*i
    const char* aG = (const char*)A + ((size_t)(bm + row0) * K_DIM + (size_t)seg * 8) * 2;
    const char* bG = (const char*)W + ((size_t)(bn + row0) * K_DIM + (size_t)seg * 8) * 2;
    uint32_t a_off[4], b_off[4];
#pragma unroll
    for (int i = 0; i < 4; i++) {
        a_off[i] = ((row0 + i * 32) * SSTRIDE + seg * 4) * 4;             // bytes
        b_off[i] = (B_BASE + (row0 + i * 32) * SSTRIDE + seg * 4) * 4;
    }

    auto load_stage = [&](int kb, int buf) {
        const size_t koff = (size_t)kb * (BK * 2);   // 128 B of K per stage
        const uint32_t sbase = sb + buf * (STAGE_WORDS * 4);
#pragma unroll
        for (int i = 0; i < 4; i++)
            cp_async16(sbase + a_off[i], aG + (size_t)(i * 32) * K_DIM * 2 + koff);
#pragma unroll
        for (int i = 0; i < 4; i++)
            cp_async16(sbase + b_off[i], bG + (size_t)(i * 32) * K_DIM * 2 + koff);
        CP_COMMIT();
    };

    // Prologue: stages 0,1 in flight.
    load_stage(0, 0);
    load_stage(1, 1);

    for (int kb = 0; kb < NUM_KB; kb++) {
        if (kb + 2 < NUM_KB) load_stage(kb + 2, (kb + 2) % STAGES);
        const int rem = NUM_KB - 1 - kb;
        if (rem >= 2)      CP_WAIT(2);
        else if (rem == 1) CP_WAIT(1);
        else               CP_WAIT(0);
        __syncthreads();   // stage kb visible to all warps

        const unsigned* As = smem + (kb % STAGES) * STAGE_WORDS;
        const unsigned* Bs = As + B_BASE;

#pragma unroll
        for (int ks = 0; ks < 4; ks++) {   // four k16 steps per BK=64
            unsigned a[4][4];
            unsigned b[4][2];
#pragma unroll
            for (int mi = 0; mi < 4; mi++) {
                const int r0 = warpRow + mi * 16 + grp;
                const unsigned* p = As + r0 * SSTRIDE + ks * 8 + tig;
                a[mi][0] = p[0];
                a[mi][1] = p[8 * SSTRIDE];
                a[mi][2] = p[4];
                a[mi][3] = p[8 * SSTRIDE + 4];
            }
#pragma unroll
            for (int ni = 0; ni < 4; ni++) {
                const int c0 = warpCol + ni * 8 + grp;
                const unsigned* p = Bs + c0 * SSTRIDE + ks * 8 + tig;
                b[ni][0] = p[0];
                b[ni][1] = p[4];
            }
#pragma unroll
            for (int mi = 0; mi < 4; mi++) {
#pragma unroll
                for (int ni = 0; ni < 4; ni++) {
                    asm volatile(
                        "mma.sync.aligned.m16n8k16.row.col.f32.bf16.bf16.f32 "
                        "{%0,%1,%2,%3}, {%4,%5,%6,%7}, {%8,%9}, {%0,%1,%2,%3};\n"
                        : "+f"(acc[mi][ni][0]), "+f"(acc[mi][ni][1]),
                          "+f"(acc[mi][ni][2]), "+f"(acc[mi][ni][3])
                        : "r"(a[mi][0]), "r"(a[mi][1]), "r"(a[mi][2]), "r"(a[mi][3]),
                          "r"(b[ni][0]), "r"(b[ni][1]));
                }
            }
        }
        __syncthreads();   // all warps done with buf kb%STAGES before it is refilled
    }

    // Epilogue: fused dequant, fp16-round, fp32 stores (proven in R7).
#pragma unroll
    for (int mi = 0; mi < 4; mi++) {
        const int r0 = bm + warpRow + mi * 16 + grp;
        const float s0 = sx[r0];
        const float s1 = sx[r0 + 8];
#pragma unroll
        for (int ni = 0; ni < 4; ni++) {
            const int c = bn + warpCol + ni * 8 + (tig << 1);
            const float w0 = ws[c];
            const float w1 = ws[c + 1];
            float2 v0 = make_float2(h16(acc[mi][ni][0] * s0 * w0),
                                    h16(acc[mi][ni][1] * s0 * w1));
            float2 v1 = make_float2(h16(acc[mi][ni][2] * s1 * w0),
                                    h16(acc[mi][ni][3] * s1 * w1));
            *reinterpret_cast<float2*>(out + (size_t)r0 * N_DIM + c)       = v0;
            *reinterpret_cast<float2*>(out + (size_t)(r0 + 8) * N_DIM + c) = v1;
        }
    }
}

// ---------------------------------------------------------------------------
extern "C" void kernel_launch(void* const* d_in, const int* in_sizes, int n_in,
                              void* d_out, int out_size) {
    // Resolve inputs BY ELEMENT COUNT (pairwise distinct; int8 arrives as int32).
    const int* pqx32 = nullptr;
    const int* wq32  = nullptr;
    const float* sx  = nullptr;
    const float* ws  = nullptr;
    for (int i = 0; i < n_in; i++) {
        long long s = (long long)in_sizes[i];
        if      (s == (long long)T_DIM * KPACK) pqx32 = (const int*)d_in[i];
        else if (s == (long long)N_DIM * KPACK) wq32  = (const int*)d_in[i];
        else if (s == (long long)T_DIM)         sx    = (const float*)d_in[i];
        else if (s == (long long)N_DIM)         ws    = (const float*)d_in[i];
    }
    if (!pqx32 || !wq32 || !sx || !ws) {
        pqx32 = (const int*)d_in[0];
        sx    = (const float*)d_in[1];
        wq32  = (const int*)d_in[2];
        ws    = (const float*)d_in[3];
    }
    float* out = (float*)d_out;

    __nv_bfloat16* a_dev = nullptr;
    __nv_bfloat16* w_dev = nullptr;
    cudaGetSymbolAddress((void**)&a_dev, g_a);
    cudaGetSymbolAddress((void**)&w_dev, g_w);

    // Prologue: int4 (delivered as int32) -> planar bf16, once per element.
    const int n4_a = (T_DIM * KPACK) / 4;   // 2,097,152 -> grid 8192
    const int n4_b = (N_DIM * KPACK) / 4;   // 5,636,096 -> grid 22016
    repack_bf16_kernel<<<n4_a / 256, 256>>>(pqx32, (unsigned*)a_dev, n4_a);
    repack_bf16_kernel<<<n4_b / 256, 256>>>(wq32,  (unsigned*)w_dev, n4_b);

    cudaFuncSetAttribute(gemm_hmma_pipe_kernel,
                         cudaFuncAttributeMaxDynamicSharedMemorySize,
                         SMEM_WORDS * 4);
    dim3 grid(N_DIM / BN, T_DIM / BM);   // 86 x 32
    gemm_hmma_pipe_kernel<<<grid, THREADS, SMEM_WORDS * 4>>>(a_dev, sx, w_dev, ws, out);
}